// round 9
// baseline (speedup 1.0000x reference)
#include <cuda_runtime.h>
#include <math.h>

#define D_DIM   1024
#define E_DIM   64
#define TOPK    8
#define BM      256
#define BK      8
#define NTILES  (D_DIM / BK)          // 128
#define TILES_PER_CHUNK 32            // 256-k chunks (reference-matching)
#define NTHREADS 128
#define XS_STRIDE 12                  // floats per x row (8 data + 4 pad)
#define XBUF_FLOATS (BM * XS_STRIDE)            // 3072
#define WS_KSTRIDE 80                 // 4 expert-groups at +20 floats
#define WBUF_FLOATS (BK * WS_KSTRIDE)           // 640
#define BUF_FLOATS (XBUF_FLOATS + WBUF_FLOATS)  // 3712
#define TOT_OFF (2 * BUF_FLOATS)                // 7424 floats (8B aligned)
#define TOT_USTRIDE 65                // u64 stride per thread
#define SMEM_FLOATS (TOT_OFF + NTHREADS * TOT_USTRIDE * 2)   // 24064
#define LS_STRIDE 66                  // epilogue overlay stride

// global scratch (allocation-free per harness rules)
__device__ int   g_counts[E_DIM];
__device__ int   g_done;
__device__ float Wt[D_DIM * E_DIM];   // W transposed: Wt[k][e]

__device__ __forceinline__ unsigned long long pack2(float a, float b) {
    unsigned long long r;
    asm("mov.b64 %0, {%1, %2};" : "=l"(r) : "f"(a), "f"(b));
    return r;
}
__device__ __forceinline__ void fma2(unsigned long long& d,
                                     unsigned long long a,
                                     unsigned long long b) {
    // packed 2x fp32 FMA (per-lane IEEE fp32) -- same math as scalar FFMA
    asm("fma.rn.f32x2 %0, %1, %2, %3;" : "=l"(d) : "l"(a), "l"(b), "l"(d));
}
__device__ __forceinline__ void add2(unsigned long long& d,
                                     unsigned long long a) {
    asm("add.rn.f32x2 %0, %0, %1;" : "+l"(d) : "l"(a));
}
__device__ __forceinline__ void cpa16(unsigned dst, const float* src) {
    asm volatile("cp.async.cg.shared.global [%0], [%1], 16;"
                 :: "r"(dst), "l"(src));
}

// One-shot (per launch) W transpose: read coalesced along k, write [k][e].
__global__ void transpose_w_kernel(const float* __restrict__ W) {
    int idx = blockIdx.x * blockDim.x + threadIdx.x;   // = e*D + k
    int e = idx >> 10, k = idx & (D_DIM - 1);
    Wt[k * E_DIM + e] = W[idx];
}

__global__ __launch_bounds__(NTHREADS, 2)
void gate_kernel(const float* __restrict__ x, const float* __restrict__ b,
                 const float* __restrict__ eu,
                 float* __restrict__ out_idx, float* __restrict__ out_gate,
                 float* __restrict__ out_var, float invN) {
    extern __shared__ __align__(16) float pool[];
    __shared__ float bsh[E_DIM];
    __shared__ int hist[E_DIM];
    __shared__ int lastFlag;

    unsigned long long* tot = (unsigned long long*)(pool + TOT_OFF);
    float* Ls = pool;                                 // epilogue overlay

    const int tid = threadIdx.x;
    const int tx  = tid & 3;       // experts tx*16 .. tx*16+15
    const int tyg = tid >> 2;      // row base; thread rows = 32*r + tyg
    const int row0 = blockIdx.x * BM;

    if (tid < E_DIM) { bsh[tid] = b[tid]; hist[tid] = 0; }

    unsigned long long acc[8][8];   // [row][expert-pair] current 256-chunk
#pragma unroll
    for (int r = 0; r < 8; r++)
#pragma unroll
        for (int j = 0; j < 8; j++) acc[r][j] = 0ULL;

    unsigned long long* totp = tot + (size_t)tid * TOT_USTRIDE;

    // ---- cp.async staging maps (fixed per thread) ----
    const float* xsrc[4];
    unsigned xdst[4];
#pragma unroll
    for (int i = 0; i < 4; i++) {
        int qq = tid + i * 128;              // 512 16B x-chunks per tile
        int row = qq >> 1, c = (qq & 1) << 2;
        xsrc[i] = x + (size_t)(row0 + row) * D_DIM + c;
        xdst[i] = (unsigned)((row * XS_STRIDE + c) * 4);
    }
    const float* wsrc = Wt + (size_t)(tid >> 4) * E_DIM
                        + (((tid >> 2) & 3) * 16) + ((tid & 3) * 4);
    const unsigned wdst = (unsigned)(((tid >> 4) * WS_KSTRIDE
                        + ((tid >> 2) & 3) * 20 + (tid & 3) * 4) * 4);

    const unsigned smem0 = (unsigned)__cvta_generic_to_shared(pool);

    // preload tile 0
    {
#pragma unroll
        for (int i = 0; i < 4; i++) cpa16(smem0 + xdst[i], xsrc[i]);
        cpa16(smem0 + XBUF_FLOATS * 4 + wdst, wsrc);
        asm volatile("cp.async.commit_group;" ::: "memory");
    }

#pragma unroll 1
    for (int tile = 0; tile < NTILES; tile++) {
        // issue next tile into the other buffer (prev consumers synced)
        if (tile + 1 < NTILES) {
            const int kb = (tile + 1) * BK;
            const unsigned base = smem0 + ((tile + 1) & 1) * (BUF_FLOATS * 4);
#pragma unroll
            for (int i = 0; i < 4; i++) cpa16(base + xdst[i], xsrc[i] + kb);
            cpa16(base + XBUF_FLOATS * 4 + wdst, wsrc + (size_t)kb * E_DIM);
            asm volatile("cp.async.commit_group;" ::: "memory");
            asm volatile("cp.async.wait_group 1;" ::: "memory");
        } else {
            asm volatile("cp.async.wait_group 0;" ::: "memory");
        }
        __syncthreads();   // tile's data visible to all threads

        const float* xsb = pool + (tile & 1) * BUF_FLOATS;
        const float* wsb = xsb + XBUF_FLOATS;
        // ---- compute: per k: 8 LDS.32(x) + 4 LDS.128(w) + 64 FFMA2 ----
#pragma unroll
        for (int k = 0; k < BK; k++) {
            const unsigned long long* wr8 =
                (const unsigned long long*)(wsb + k * WS_KSTRIDE + tx * 20);
            ulonglong2 w0 = *(const ulonglong2*)(wr8 + 0);
            ulonglong2 w1 = *(const ulonglong2*)(wr8 + 2);
            ulonglong2 w2 = *(const ulonglong2*)(wr8 + 4);
            ulonglong2 w3 = *(const ulonglong2*)(wr8 + 6);
#pragma unroll
            for (int r = 0; r < 8; r++) {
                float xv = xsb[(r * 32 + tyg) * XS_STRIDE + k];
                unsigned long long xd = pack2(xv, xv);
                fma2(acc[r][0], xd, w0.x); fma2(acc[r][1], xd, w0.y);
                fma2(acc[r][2], xd, w1.x); fma2(acc[r][3], xd, w1.y);
                fma2(acc[r][4], xd, w2.x); fma2(acc[r][5], xd, w2.y);
                fma2(acc[r][6], xd, w3.x); fma2(acc[r][7], xd, w3.y);
            }
        }
        // ---- 256-k chunk folds: tot = ((P0+P1)+P2)+P3 ----
        if ((tile & (TILES_PER_CHUNK - 1)) == (TILES_PER_CHUNK - 1)) {
            const int ch = tile / TILES_PER_CHUNK;
            if (ch == 0) {
#pragma unroll
                for (int r = 0; r < 8; r++)
#pragma unroll
                    for (int j = 0; j < 8; j++) {
                        totp[r * 8 + j] = acc[r][j];
                        acc[r][j] = 0ULL;
                    }
            } else if (ch < 3) {
#pragma unroll
                for (int r = 0; r < 8; r++)
#pragma unroll
                    for (int j = 0; j < 8; j++) {
                        unsigned long long t = totp[r * 8 + j];
                        add2(t, acc[r][j]);
                        totp[r * 8 + j] = t;
                        acc[r][j] = 0ULL;
                    }
            } else {   // final fold: keep total in registers
#pragma unroll
                for (int r = 0; r < 8; r++)
#pragma unroll
                    for (int j = 0; j < 8; j++) {
                        unsigned long long t = totp[r * 8 + j];
                        add2(t, acc[r][j]);
                        acc[r][j] = t;
                    }
            }
        }
        __syncthreads();   // all consumers done before buffer reuse
    }

    // ---- spill biased logits: Ls[row][expert], stride 66 ----
#pragma unroll
    for (int r = 0; r < 8; r++) {
        int row = r * 32 + tyg;
#pragma unroll
        for (int j = 0; j < 8; j++) {
            int ec = tx * 16 + j * 2;
            float lo = __uint_as_float((unsigned)(acc[r][j] & 0xffffffffULL));
            float hi = __uint_as_float((unsigned)(acc[r][j] >> 32));
            Ls[(size_t)row * LS_STRIDE + ec]     = lo + bsh[ec];
            Ls[(size_t)row * LS_STRIDE + ec + 1] = hi + bsh[ec + 1];
        }
    }
    __syncthreads();

#pragma unroll 1
    for (int half = 0; half < 2; half++) {
        const int lrow = tid + half * 128;
        const int row = row0 + lrow;
        float* L = Ls + (size_t)lrow * LS_STRIDE;
        float mx = L[0];
#pragma unroll
        for (int e = 1; e < E_DIM; e++) mx = fmaxf(mx, L[e]);
        float s = 0.f;
#pragma unroll
        for (int e = 0; e < E_DIM; e++) s += expf(L[e] - mx);
        float inv = 1.f / s;
        // top-8 by raw logits; strict >, lowest index ties (lax.top_k)
        const float NEG_INF = __int_as_float(0xff800000);
        unsigned long long used = 0ULL;
        float gv[TOPK]; int gi[TOPK];
        float gs = 0.f;
#pragma unroll
        for (int j = 0; j < TOPK; j++) {
            float best = NEG_INF; int bi = 0;
            for (int e = 0; e < E_DIM; e++) {
                float v = L[e];
                if (!((used >> e) & 1ULL) && v > best) { best = v; bi = e; }
            }
            used |= (1ULL << bi);
            float g = expf(best - mx) * inv;
            gv[j] = g; gi[j] = bi; gs += g;
            atomicAdd(&hist[bi], 1);
        }
        float rn = 1.f / (gs + 1e-8f);
#pragma unroll
        for (int j = 0; j < TOPK; j++) {
            out_idx[(size_t)row * TOPK + j]  = (float)gi[j];
            out_gate[(size_t)row * TOPK + j] = gv[j] * rn;
        }
    }
    __syncthreads();
    if (tid < E_DIM) atomicAdd(&g_counts[tid], hist[tid]);

    // ---- fused finisher: last CTA computes EMA-usage variance ----
    __syncthreads();
    if (tid == 0) {
        __threadfence();
        int old = atomicAdd(&g_done, 1);
        lastFlag = (old == (int)gridDim.x - 1);
    }
    __syncthreads();
    if (lastFlag && tid == 0) {
        float u[E_DIM];
        float m = 0.f;
        for (int e = 0; e < E_DIM; e++) {
            int c = atomicExch(&g_counts[e], 0);   // read + reset for replay
            u[e] = 0.95f * eu[e] + 0.05f * ((float)c * invN);
            m += u[e];
        }
        m *= (1.f / E_DIM);
        float v = 0.f;
        for (int e = 0; e < E_DIM; e++) {
            float d = u[e] - m;
            v += d * d;
        }
        *out_var = v * (1.f / (E_DIM - 1));   // ddof=1
        atomicExch(&g_done, 0);               // reset for next replay
    }
}

extern "C" void kernel_launch(void* const* d_in, const int* in_sizes, int n_in,
                              void* d_out, int out_size) {
    const float* x  = (const float*)d_in[0];
    const float* W  = (const float*)d_in[1];
    const float* b  = (const float*)d_in[2];
    const float* eu = (const float*)d_in[3];
    const int N = in_sizes[0] / D_DIM;   // 262144

    float* out      = (float*)d_out;
    float* out_idx  = out;                        // [N,8] indices (as float)
    float* out_gate = out + (size_t)N * TOPK;     // [N,8] gates
    float* out_var  = out + (out_size - 1);       // scalar variance

    static int smem_set = 0;
    if (!smem_set) {
        cudaFuncSetAttribute(gate_kernel,
                             cudaFuncAttributeMaxDynamicSharedMemorySize,
                             SMEM_FLOATS * 4);
        smem_set = 1;
    }

    transpose_w_kernel<<<(E_DIM * D_DIM) / 256, 256>>>(W);
    gate_kernel<<<N / BM, NTHREADS, SMEM_FLOATS * 4>>>(
        x, b, eu, out_idx, out_gate, out_var, 1.f / (float)N);
}